// round 7
// baseline (speedup 1.0000x reference)
#include <cuda_runtime.h>
#include <cstdint>

#define N 8192
#define NW 128          // max 64-bit words per active mask row (N/64)
typedef unsigned long long u64;
typedef unsigned int u32;
typedef long long s64;

// ---------------- device globals (zero-initialized at module load) ----------------
__device__ u32 g_maxbox;
__device__ int g_cnt;      // valid boxes (score > 0.25)
__device__ int g_cnt_a;    // active valid boxes (positive area)
__device__ float g_x1[N], g_y1[N], g_x2[N], g_y2[N], g_sc[N];
__device__ u64 g_keys[N];  // (~mono(score))<<32 | idx<<1 | act   -- full-u64 comparable
__device__ float g_sx1[N], g_sy1[N], g_sx2[N], g_sy2[N], g_ssc[N], g_sar[N]; // sorted actives
__device__ int g_apos[N];  // sorted-active rank -> overall sorted position (output row)
__device__ u64 g_mask[N * NW];   // suppression bitmask among actives

__device__ __forceinline__ u32 fmono(float f) {
    u32 u = __float_as_uint(f);
    return (u & 0x80000000u) ? ~u : (u | 0x80000000u);
}

// decode boxes, coord max, warp-aggregated compaction of valid keys, zero output
__global__ void k_prep(const float* __restrict__ p, float* __restrict__ out) {
    int i = blockIdx.x * blockDim.x + threadIdx.x;   // grid covers exactly N
    float cx = p[i], cy = p[N + i], pw = p[2*N + i], ph = p[3*N + i], s = p[4*N + i];
    float x1 = cx - pw*0.5f, y1 = cy - ph*0.5f, x2 = cx + pw*0.5f, y2 = cy + ph*0.5f;
    g_x1[i]=x1; g_y1[i]=y1; g_x2[i]=x2; g_y2[i]=y2; g_sc[i]=s;

    int lane = threadIdx.x & 31;
    u32 m = fmono(fmaxf(fmaxf(x1,x2), fmaxf(y1,y2)));
    #pragma unroll
    for (int o = 16; o; o >>= 1) m = max(m, __shfl_xor_sync(0xffffffffu, m, o));
    if (lane == 0) atomicMax(&g_maxbox, m);

    bool valid = s > 0.25f;
    bool act = valid && (x2 > x1) && (y2 > y1);
    u32 vb = __ballot_sync(0xffffffffu, valid);
    u32 ab = __ballot_sync(0xffffffffu, act);
    if (vb) {
        int leader = __ffs(vb) - 1;
        int base = 0;
        if (lane == leader) {
            base = atomicAdd(&g_cnt, __popc(vb));
            if (ab) atomicAdd(&g_cnt_a, __popc(ab));
        }
        base = __shfl_sync(0xffffffffu, base, leader);
        if (valid) {
            int slot = base + __popc(vb & ((1u << lane) - 1u));
            g_keys[slot] = ((u64)(~fmono(s)) << 32) | ((u32)i << 1) | (act ? 1u : 0u);
        }
    }
    for (int k = i; k < N*6; k += N) out[k] = 0.0f;   // zero full output
}

// O(n^2) rank sort: 32 i per block, j-loop split 8 ways -> ~103 active blocks.
// Passive boxes (zero area) never interact -> emitted directly here.
__global__ __launch_bounds__(256) void k_rank(float* __restrict__ out) {
    __shared__ u64 sk[2048];
    int cnt = g_cnt;
    if (blockIdx.x * 32 >= cnt) return;
    int tid = threadIdx.x;
    int i = blockIdx.x * 32 + (tid >> 3);
    int part = tid & 7;

    u64 ki = (i < cnt) ? g_keys[i] : ~0ull;
    int rank_all = 0, rank_act = 0;

    for (int base = 0; base < cnt; base += 2048) {
        int lim = min(2048, cnt - base);
        __syncthreads();
        for (int t = tid; t < lim; t += 256) sk[t] = g_keys[base + t];
        __syncthreads();
        for (int j = part; j < lim; j += 8) {
            u64 kj = sk[j];
            int lt = kj < ki;                      // full-u64 compare, no masking
            rank_all += lt;
            rank_act += lt & (int)(kj & 1ull);
        }
    }
    #pragma unroll
    for (int o = 1; o < 8; o <<= 1) {
        rank_all += __shfl_xor_sync(0xffffffffu, rank_all, o);
        rank_act += __shfl_xor_sync(0xffffffffu, rank_act, o);
    }

    if (part == 0 && i < cnt) {
        int o = (int)((ki >> 1) & 0x1FFFull);
        bool act = (ki & 1ull) != 0ull;
        float x1 = g_x1[o], y1 = g_y1[o], x2 = g_x2[o], y2 = g_y2[o], s = g_sc[o];
        if (act) {
            int r = rank_act;
            g_sx1[r]=x1; g_sy1[r]=y1; g_sx2[r]=x2; g_sy2[r]=y2;
            g_ssc[r]=s;  g_sar[r]=(x2-x1)*(y2-y1);
            g_apos[r]=rank_all;
        } else {
            float f = (g_maxbox <= 0xBF800000u) ? 1.0f : (1.0f / 416.0f);
            float* o6 = out + rank_all * 6;
            o6[0]=x1*f; o6[1]=y1*f; o6[2]=x2*f; o6[3]=y2*f; o6[4]=s; o6[5]=0.0f;
        }
    }
}

// pairwise IoU bitmask among actives: grid-stride over actual upper-triangle tiles
__global__ __launch_bounds__(256) void k_mask() {
    int cnt = g_cnt_a;
    if (cnt == 0) return;
    int W = (cnt + 63) >> 6;
    int itiles = (cnt + 15) >> 4;
    int wtiles = (W + 15) >> 4;
    int ntiles = itiles * wtiles;

    __shared__ float jx1[1040], jy1[1040], jx2[1040], jy2[1040], jar[1040];
    int tid = threadIdx.x;

    for (int t = blockIdx.x; t < ntiles; t += gridDim.x) {
        int i0 = (t / wtiles) * 16;
        int w0 = (t % wtiles) * 16;
        if ((w0 + 16) * 64 <= i0) continue;   // fully below diagonal (uniform per block)

        __syncthreads();                       // smem reuse guard
        for (int tt = tid; tt < 1024; tt += 256) {
            int j = w0 * 64 + tt;
            int jm = (tt >> 6) * 65 + (tt & 63);   // +1 pad per 64 -> conflict-free
            bool ok = j < cnt;
            jx1[jm] = ok ? g_sx1[j] :  3.4e38f;
            jy1[jm] = ok ? g_sy1[j] :  3.4e38f;
            jx2[jm] = ok ? g_sx2[j] : -3.4e38f;
            jy2[jm] = ok ? g_sy2[j] : -3.4e38f;
            jar[jm] = ok ? g_sar[j] : 0.0f;
        }
        __syncthreads();

        int r  = tid >> 4;          // row within tile
        int wl = tid & 15;          // word within tile
        int i = i0 + r;
        int w = w0 + wl;
        if (i < cnt && w < W) {
            float ix1 = g_sx1[i], iy1 = g_sy1[i], ix2 = g_sx2[i], iy2 = g_sy2[i], iar = g_sar[i];
            int base = wl * 65;
            u64 bits = 0;
            #pragma unroll 8
            for (int jj = 0; jj < 64; jj++) {
                float bx1 = jx1[base + jj], by1 = jy1[base + jj];
                float bx2 = jx2[base + jj], by2 = jy2[base + jj], ba = jar[base + jj];
                float xx1 = fmaxf(ix1, bx1), yy1 = fmaxf(iy1, by1);
                float xx2 = fminf(ix2, bx2), yy2 = fminf(iy2, by2);
                float dx = fmaxf(xx2 - xx1, 0.0f), dy = fmaxf(yy2 - yy1, 0.0f);
                float inter = dx * dy;
                float uni = iar + ba - inter;
                bool pred = (inter > 0.45f * uni) && (uni > 0.0f);
                bits |= ((u64)pred) << jj;
            }
            g_mask[(size_t)i * NW + w] = bits;
        }
    }
}

// two-phase pipelined greedy scan.
// Phase A: warp0 resolves chunk c (splat-trick branchless chain, ~6 instr/bit);
//          warps1-3 emit chunk c-1, apply its kb to words >= c+1, prefetch c+1.
// Phase B: 64 threads apply kb_c to word c+1 from the prefetched nextbuf
//          (sparse atomicOr) -> s_remv[c+1] complete before iteration c+1.
__global__ __launch_bounds__(128) void k_scan(float* __restrict__ out) {
    __shared__ u64 colbuf[2][64];    // rows of chunk c at word c   (resolve input)
    __shared__ u64 nextbuf[2][64];   // rows of chunk c at word c+1 (phase-B input)
    __shared__ u64 s_remv[NW];
    __shared__ u64 s_kb[2];
    int tid = threadIdx.x;
    int cnt = g_cnt_a;
    int W = (cnt + 63) >> 6;
    float f = (g_maxbox <= 0xBF800000u) ? 1.0f : (1.0f / 416.0f);

    for (int w = tid; w < NW; w += 128) s_remv[w] = 0ull;
    if (tid < 64 && W > 0) {
        colbuf[0][tid]  = (tid < cnt) ? g_mask[(size_t)tid * NW + 0] : 0ull;
        nextbuf[0][tid] = (W > 1 && tid < cnt) ? g_mask[(size_t)tid * NW + 1] : 0ull;
    }
    __syncthreads();

    for (int c = 0; c < W; c++) {
        int cb = c & 1;
        if (tid < 32) {
            // ---- serial branchless resolve of chunk c (all lanes redundant) ----
            u64 sup = s_remv[c];
            u64 kb = 0;
            const u64* col = colbuf[cb];
            #pragma unroll
            for (int b = 0; b < 64; b++) {
                u64 splat = (u64)(((s64)(sup << (63 - b))) >> 63); // all-ones if bit b suppressed
                kb |= (~splat) & (1ull << b);
                sup |= col[b] & ~splat;
            }
            int lim = cnt - c * 64;
            if (lim < 64) kb &= (1ull << lim) - 1ull;
            if (tid == 0) s_kb[cb] = kb;
        } else {
            int t = tid - 32;        // 0..95
            if (c >= 1) {
                u64 kbp = s_kb[1 - cb];
                // emit chunk c-1's kept rows
                if (t < 64) {
                    int k = (c - 1) * 64 + t;
                    if (k < cnt && ((kbp >> t) & 1ull)) {
                        float* o = out + g_apos[k] * 6;
                        *(float2*)(o)     = make_float2(g_sx1[k] * f, g_sy1[k] * f);
                        *(float2*)(o + 2) = make_float2(g_sx2[k] * f, g_sy2[k] * f);
                        *(float2*)(o + 4) = make_float2(g_ssc[k], 0.0f);
                    }
                }
                // apply chunk c-1 to words >= c+1 (word c was done in its phase B)
                int g = t & 7;
                size_t rb = (size_t)(c - 1) * 64;
                for (int w = c + 1 + (t >> 3); w < W; w += 12) {
                    u64 acc = 0;
                    #pragma unroll
                    for (int b2 = 0; b2 < 8; b2++) {
                        int b = g * 8 + b2;
                        acc |= g_mask[(rb + b) * NW + w] & (0ull - ((kbp >> b) & 1ull));
                    }
                    if (acc) atomicOr(&s_remv[w], acc);
                }
            }
            // prefetch chunk c+1 columns
            if (c + 1 < W) {
                if (t < 64) {
                    int r = (c + 1) * 64 + t;
                    colbuf[1 - cb][t] = (r < cnt) ? g_mask[(size_t)r * NW + (c + 1)] : 0ull;
                } else {
                    #pragma unroll
                    for (int h = 0; h < 2; h++) {
                        int rr = (t - 64) * 2 + h;
                        int r = (c + 1) * 64 + rr;
                        nextbuf[1 - cb][rr] =
                            (c + 2 < W && r < cnt) ? g_mask[(size_t)r * NW + (c + 2)] : 0ull;
                    }
                }
            }
        }
        __syncthreads();

        // ---- phase B: apply kb_c to word c+1 from prefetched nextbuf ----
        if (c + 1 < W && tid < 64) {
            u64 kb = s_kb[cb];
            u64 v = nextbuf[cb][tid] & (0ull - ((kb >> tid) & 1ull));
            if (v) atomicOr(&s_remv[c + 1], v);
        }
        __syncthreads();
    }

    // epilogue: emit last chunk's kept rows
    if (W > 0 && tid < 64) {
        u64 kbl = s_kb[(W - 1) & 1];
        int k = (W - 1) * 64 + tid;
        if (k < cnt && ((kbl >> tid) & 1ull)) {
            float* o = out + g_apos[k] * 6;
            *(float2*)(o)     = make_float2(g_sx1[k] * f, g_sy1[k] * f);
            *(float2*)(o + 2) = make_float2(g_sx2[k] * f, g_sy2[k] * f);
            *(float2*)(o + 4) = make_float2(g_ssc[k], 0.0f);
        }
    }

    // reset counters for the next graph replay
    if (tid == 0) { g_cnt = 0; g_cnt_a = 0; g_maxbox = 0u; }
}

extern "C" void kernel_launch(void* const* d_in, const int* in_sizes, int n_in,
                              void* d_out, int out_size) {
    const float* preds = (const float*)d_in[0];
    float* out = (float*)d_out;

    k_prep<<<N / 256, 256>>>(preds, out);
    k_rank<<<256, 256>>>(out);          // 32 i per block; excess blocks exit
    k_mask<<<128, 256>>>();
    k_scan<<<1, 128>>>(out);
}

// round 8
// speedup vs baseline: 1.0039x; 1.0039x over previous
#include <cuda_runtime.h>
#include <cstdint>

#define N 8192
#define NW 128          // max 64-bit words per active mask row (N/64)
typedef unsigned long long u64;
typedef unsigned int u32;

// ---------------- device globals (zero-initialized at module load) ----------------
__device__ u32 g_maxbox;
__device__ int g_cnt;      // valid boxes (score > 0.25)
__device__ int g_cnt_a;    // active valid boxes (positive area)
__device__ float g_x1[N], g_y1[N], g_x2[N], g_y2[N], g_sc[N];
__device__ u64 g_keys[N];  // (~mono(score))<<32 | idx<<1 | act   -- full-u64 comparable
__device__ float g_sx1[N], g_sy1[N], g_sx2[N], g_sy2[N], g_ssc[N], g_sar[N]; // sorted actives
__device__ int g_apos[N];  // sorted-active rank -> overall sorted position (output row)
__device__ u64 g_mask[N * NW];   // suppression bitmask among actives

__device__ __forceinline__ u32 fmono(float f) {
    u32 u = __float_as_uint(f);
    return (u & 0x80000000u) ? ~u : (u | 0x80000000u);
}

// decode boxes, coord max, warp-aggregated compaction of valid keys, zero output
__global__ void k_prep(const float* __restrict__ p, float* __restrict__ out) {
    int i = blockIdx.x * blockDim.x + threadIdx.x;   // grid covers exactly N
    float cx = p[i], cy = p[N + i], pw = p[2*N + i], ph = p[3*N + i], s = p[4*N + i];
    float x1 = cx - pw*0.5f, y1 = cy - ph*0.5f, x2 = cx + pw*0.5f, y2 = cy + ph*0.5f;
    g_x1[i]=x1; g_y1[i]=y1; g_x2[i]=x2; g_y2[i]=y2; g_sc[i]=s;

    int lane = threadIdx.x & 31;
    u32 m = fmono(fmaxf(fmaxf(x1,x2), fmaxf(y1,y2)));
    #pragma unroll
    for (int o = 16; o; o >>= 1) m = max(m, __shfl_xor_sync(0xffffffffu, m, o));
    if (lane == 0) atomicMax(&g_maxbox, m);

    bool valid = s > 0.25f;
    bool act = valid && (x2 > x1) && (y2 > y1);
    u32 vb = __ballot_sync(0xffffffffu, valid);
    u32 ab = __ballot_sync(0xffffffffu, act);
    if (vb) {
        int leader = __ffs(vb) - 1;
        int base = 0;
        if (lane == leader) {
            base = atomicAdd(&g_cnt, __popc(vb));
            if (ab) atomicAdd(&g_cnt_a, __popc(ab));
        }
        base = __shfl_sync(0xffffffffu, base, leader);
        if (valid) {
            int slot = base + __popc(vb & ((1u << lane) - 1u));
            g_keys[slot] = ((u64)(~fmono(s)) << 32) | ((u32)i << 1) | (act ? 1u : 0u);
        }
    }
    for (int k = i; k < N*6; k += N) out[k] = 0.0f;   // zero full output
}

// O(n^2) rank sort: 32 i per block, j-loop split 8 ways -> ~103 active blocks.
// Passive boxes (zero area) never interact -> emitted directly here.
__global__ __launch_bounds__(256) void k_rank(float* __restrict__ out) {
    __shared__ u64 sk[2048];
    int cnt = g_cnt;
    if (blockIdx.x * 32 >= cnt) return;
    int tid = threadIdx.x;
    int i = blockIdx.x * 32 + (tid >> 3);
    int part = tid & 7;

    u64 ki = (i < cnt) ? g_keys[i] : ~0ull;
    int rank_all = 0, rank_act = 0;

    for (int base = 0; base < cnt; base += 2048) {
        int lim = min(2048, cnt - base);
        __syncthreads();
        for (int t = tid; t < lim; t += 256) sk[t] = g_keys[base + t];
        __syncthreads();
        for (int j = part; j < lim; j += 8) {
            u64 kj = sk[j];
            int lt = kj < ki;                      // full-u64 compare, no masking
            rank_all += lt;
            rank_act += lt & (int)(kj & 1ull);
        }
    }
    #pragma unroll
    for (int o = 1; o < 8; o <<= 1) {
        rank_all += __shfl_xor_sync(0xffffffffu, rank_all, o);
        rank_act += __shfl_xor_sync(0xffffffffu, rank_act, o);
    }

    if (part == 0 && i < cnt) {
        int o = (int)((ki >> 1) & 0x1FFFull);
        bool act = (ki & 1ull) != 0ull;
        float x1 = g_x1[o], y1 = g_y1[o], x2 = g_x2[o], y2 = g_y2[o], s = g_sc[o];
        if (act) {
            int r = rank_act;
            g_sx1[r]=x1; g_sy1[r]=y1; g_sx2[r]=x2; g_sy2[r]=y2;
            g_ssc[r]=s;  g_sar[r]=(x2-x1)*(y2-y1);
            g_apos[r]=rank_all;
        } else {
            float f = (g_maxbox <= 0xBF800000u) ? 1.0f : (1.0f / 416.0f);
            float* o6 = out + rank_all * 6;
            o6[0]=x1*f; o6[1]=y1*f; o6[2]=x2*f; o6[3]=y2*f; o6[4]=s; o6[5]=0.0f;
        }
    }
}

// pairwise IoU bitmask among actives: grid-stride over actual upper-triangle tiles
__global__ __launch_bounds__(256) void k_mask() {
    int cnt = g_cnt_a;
    if (cnt == 0) return;
    int W = (cnt + 63) >> 6;
    int itiles = (cnt + 15) >> 4;
    int wtiles = (W + 15) >> 4;
    int ntiles = itiles * wtiles;

    __shared__ float jx1[1040], jy1[1040], jx2[1040], jy2[1040], jar[1040];
    int tid = threadIdx.x;

    for (int t = blockIdx.x; t < ntiles; t += gridDim.x) {
        int i0 = (t / wtiles) * 16;
        int w0 = (t % wtiles) * 16;
        if ((w0 + 16) * 64 <= i0) continue;   // fully below diagonal (uniform per block)

        __syncthreads();                       // smem reuse guard
        for (int tt = tid; tt < 1024; tt += 256) {
            int j = w0 * 64 + tt;
            int jm = (tt >> 6) * 65 + (tt & 63);   // +1 pad per 64 -> conflict-free
            bool ok = j < cnt;
            jx1[jm] = ok ? g_sx1[j] :  3.4e38f;
            jy1[jm] = ok ? g_sy1[j] :  3.4e38f;
            jx2[jm] = ok ? g_sx2[j] : -3.4e38f;
            jy2[jm] = ok ? g_sy2[j] : -3.4e38f;
            jar[jm] = ok ? g_sar[j] : 0.0f;
        }
        __syncthreads();

        int r  = tid >> 4;          // row within tile
        int wl = tid & 15;          // word within tile
        int i = i0 + r;
        int w = w0 + wl;
        if (i < cnt && w < W) {
            float ix1 = g_sx1[i], iy1 = g_sy1[i], ix2 = g_sx2[i], iy2 = g_sy2[i], iar = g_sar[i];
            int base = wl * 65;
            u64 bits = 0;
            #pragma unroll 8
            for (int jj = 0; jj < 64; jj++) {
                float bx1 = jx1[base + jj], by1 = jy1[base + jj];
                float bx2 = jx2[base + jj], by2 = jy2[base + jj], ba = jar[base + jj];
                float xx1 = fmaxf(ix1, bx1), yy1 = fmaxf(iy1, by1);
                float xx2 = fminf(ix2, bx2), yy2 = fminf(iy2, by2);
                float dx = fmaxf(xx2 - xx1, 0.0f), dy = fmaxf(yy2 - yy1, 0.0f);
                float inter = dx * dy;
                float uni = iar + ba - inter;
                bool pred = (inter > 0.45f * uni) && (uni > 0.0f);
                bits |= ((u64)pred) << jj;
            }
            g_mask[(size_t)i * NW + w] = bits;
        }
    }
}

// pipelined greedy scan with WARP-PARALLEL fixed-point resolve.
// keep_j = cand_j && no kept i<j suppresses j  -- unique fixed point == greedy.
// Lane l owns rows l and l+32; d_j = row j's diagonal word (IoU symmetric, so
// bits i<j of row j are "i suppresses j" -- no transpose needed). Iterate
// Jacobi/Gauss-Seidel via 2 ballots per pass until stable (<= chain depth).
__global__ __launch_bounds__(128) void k_scan(float* __restrict__ out) {
    __shared__ u64 colbuf[2][64];    // rows of chunk c at word c   (resolve input)
    __shared__ u64 nextbuf[2][64];   // rows of chunk c at word c+1 (phase-B input)
    __shared__ u64 s_remv[NW];
    __shared__ u64 s_kb[2];
    int tid = threadIdx.x;
    int cnt = g_cnt_a;
    int W = (cnt + 63) >> 6;
    float f = (g_maxbox <= 0xBF800000u) ? 1.0f : (1.0f / 416.0f);

    for (int w = tid; w < NW; w += 128) s_remv[w] = 0ull;
    if (tid < 64 && W > 0) {
        colbuf[0][tid]  = (tid < cnt) ? g_mask[(size_t)tid * NW + 0] : 0ull;
        nextbuf[0][tid] = (W > 1 && tid < cnt) ? g_mask[(size_t)tid * NW + 1] : 0ull;
    }
    __syncthreads();

    for (int c = 0; c < W; c++) {
        int cb = c & 1;
        if (tid < 32) {
            // ---- warp-parallel fixed-point resolve of chunk c ----
            int l = tid;
            u64 sup = s_remv[c];
            int lim = cnt - c * 64;
            if (lim < 64) sup |= ~((1ull << lim) - 1ull);   // tail rows = suppressed
            u64 d_lo = colbuf[cb][l];
            u64 d_hi = colbuf[cb][l + 32];
            u32 cand_lo = (u32)((sup >> l) & 1ull) ^ 1u;
            u32 cand_hi = (u32)((sup >> (l + 32)) & 1ull) ^ 1u;
            u64 below_lo = (1ull << l) - 1ull;
            u64 below_hi = (1ull << (l + 32)) - 1ull;

            u32 kl = __ballot_sync(0xffffffffu, cand_lo);
            u32 kh = __ballot_sync(0xffffffffu, cand_hi);
            while (true) {
                u64 kept = (u64)kl | ((u64)kh << 32);
                u32 nl = __ballot_sync(0xffffffffu,
                        cand_lo && ((d_lo & kept & below_lo) == 0ull));
                kept = (u64)nl | ((u64)kh << 32);            // Gauss-Seidel for hi half
                u32 nh = __ballot_sync(0xffffffffu,
                        cand_hi && ((d_hi & kept & below_hi) == 0ull));
                bool stable = (nl == kl) && (nh == kh);
                kl = nl; kh = nh;
                if (stable) break;                           // fixed point == greedy
            }
            if (tid == 0) s_kb[cb] = (u64)kl | ((u64)kh << 32);
        } else {
            int t = tid - 32;        // 0..95
            if (c >= 1) {
                u64 kbp = s_kb[1 - cb];
                // emit chunk c-1's kept rows
                if (t < 64) {
                    int k = (c - 1) * 64 + t;
                    if (k < cnt && ((kbp >> t) & 1ull)) {
                        float* o = out + g_apos[k] * 6;
                        *(float2*)(o)     = make_float2(g_sx1[k] * f, g_sy1[k] * f);
                        *(float2*)(o + 2) = make_float2(g_sx2[k] * f, g_sy2[k] * f);
                        *(float2*)(o + 4) = make_float2(g_ssc[k], 0.0f);
                    }
                }
                // apply chunk c-1 to words >= c+1 (word c was done in its phase B)
                int g = t & 7;
                size_t rb = (size_t)(c - 1) * 64;
                for (int w = c + 1 + (t >> 3); w < W; w += 12) {
                    u64 acc = 0;
                    #pragma unroll
                    for (int b2 = 0; b2 < 8; b2++) {
                        int b = g * 8 + b2;
                        acc |= g_mask[(rb + b) * NW + w] & (0ull - ((kbp >> b) & 1ull));
                    }
                    if (acc) atomicOr(&s_remv[w], acc);
                }
            }
            // prefetch chunk c+1 columns
            if (c + 1 < W) {
                if (t < 64) {
                    int r = (c + 1) * 64 + t;
                    colbuf[1 - cb][t] = (r < cnt) ? g_mask[(size_t)r * NW + (c + 1)] : 0ull;
                } else {
                    #pragma unroll
                    for (int h = 0; h < 2; h++) {
                        int rr = (t - 64) * 2 + h;
                        int r = (c + 1) * 64 + rr;
                        nextbuf[1 - cb][rr] =
                            (c + 2 < W && r < cnt) ? g_mask[(size_t)r * NW + (c + 2)] : 0ull;
                    }
                }
            }
        }
        __syncthreads();

        // ---- phase B: apply kb_c to word c+1 from prefetched nextbuf ----
        if (c + 1 < W && tid < 64) {
            u64 kb = s_kb[cb];
            u64 v = nextbuf[cb][tid] & (0ull - ((kb >> tid) & 1ull));
            if (v) atomicOr(&s_remv[c + 1], v);
        }
        __syncthreads();
    }

    // epilogue: emit last chunk's kept rows
    if (W > 0 && tid < 64) {
        u64 kbl = s_kb[(W - 1) & 1];
        int k = (W - 1) * 64 + tid;
        if (k < cnt && ((kbl >> tid) & 1ull)) {
            float* o = out + g_apos[k] * 6;
            *(float2*)(o)     = make_float2(g_sx1[k] * f, g_sy1[k] * f);
            *(float2*)(o + 2) = make_float2(g_sx2[k] * f, g_sy2[k] * f);
            *(float2*)(o + 4) = make_float2(g_ssc[k], 0.0f);
        }
    }

    // reset counters for the next graph replay
    if (tid == 0) { g_cnt = 0; g_cnt_a = 0; g_maxbox = 0u; }
}

extern "C" void kernel_launch(void* const* d_in, const int* in_sizes, int n_in,
                              void* d_out, int out_size) {
    const float* preds = (const float*)d_in[0];
    float* out = (float*)d_out;

    k_prep<<<N / 256, 256>>>(preds, out);
    k_rank<<<256, 256>>>(out);          // 32 i per block; excess blocks exit
    k_mask<<<128, 256>>>();
    k_scan<<<1, 128>>>(out);
}

// round 9
// speedup vs baseline: 1.0872x; 1.0830x over previous
#include <cuda_runtime.h>
#include <cstdint>

#define N 8192
#define NW 128          // max 64-bit words per active mask row (N/64)
#define SCAN_SMEM_WORDS 20480   // 160 KB dynamic smem budget for staged mask
typedef unsigned long long u64;
typedef unsigned int u32;

// ---------------- device globals (zero-initialized at module load) ----------------
__device__ u32 g_maxbox;
__device__ int g_cnt;      // valid boxes (score > 0.25)
__device__ int g_cnt_a;    // active valid boxes (positive area)
__device__ float g_x1[N], g_y1[N], g_x2[N], g_y2[N], g_sc[N];
__device__ u64 g_keys[N];  // (~mono(score))<<32 | idx<<1 | act   -- full-u64 comparable
__device__ float g_sx1[N], g_sy1[N], g_sx2[N], g_sy2[N], g_ssc[N], g_sar[N]; // sorted actives
__device__ int g_apos[N];  // sorted-active rank -> overall sorted position (output row)
__device__ u64 g_mask[N * NW];   // suppression bitmask among actives

__device__ __forceinline__ u32 fmono(float f) {
    u32 u = __float_as_uint(f);
    return (u & 0x80000000u) ? ~u : (u | 0x80000000u);
}

// decode boxes, coord max, warp-aggregated compaction of valid keys, zero output
__global__ void k_prep(const float* __restrict__ p, float* __restrict__ out) {
    int i = blockIdx.x * blockDim.x + threadIdx.x;   // grid covers exactly N
    float cx = p[i], cy = p[N + i], pw = p[2*N + i], ph = p[3*N + i], s = p[4*N + i];
    float x1 = cx - pw*0.5f, y1 = cy - ph*0.5f, x2 = cx + pw*0.5f, y2 = cy + ph*0.5f;
    g_x1[i]=x1; g_y1[i]=y1; g_x2[i]=x2; g_y2[i]=y2; g_sc[i]=s;

    int lane = threadIdx.x & 31;
    u32 m = fmono(fmaxf(fmaxf(x1,x2), fmaxf(y1,y2)));
    #pragma unroll
    for (int o = 16; o; o >>= 1) m = max(m, __shfl_xor_sync(0xffffffffu, m, o));
    if (lane == 0) atomicMax(&g_maxbox, m);

    bool valid = s > 0.25f;
    bool act = valid && (x2 > x1) && (y2 > y1);
    u32 vb = __ballot_sync(0xffffffffu, valid);
    u32 ab = __ballot_sync(0xffffffffu, act);
    if (vb) {
        int leader = __ffs(vb) - 1;
        int base = 0;
        if (lane == leader) {
            base = atomicAdd(&g_cnt, __popc(vb));
            if (ab) atomicAdd(&g_cnt_a, __popc(ab));
        }
        base = __shfl_sync(0xffffffffu, base, leader);
        if (valid) {
            int slot = base + __popc(vb & ((1u << lane) - 1u));
            g_keys[slot] = ((u64)(~fmono(s)) << 32) | ((u32)i << 1) | (act ? 1u : 0u);
        }
    }
    for (int k = i; k < N*6; k += N) out[k] = 0.0f;   // zero full output
}

// O(n^2) rank sort: 32 i per block, j-loop split 8 ways -> ~103 active blocks.
// Passive boxes (zero area) never interact -> emitted directly here.
__global__ __launch_bounds__(256) void k_rank(float* __restrict__ out) {
    __shared__ u64 sk[2048];
    int cnt = g_cnt;
    if (blockIdx.x * 32 >= cnt) return;
    int tid = threadIdx.x;
    int i = blockIdx.x * 32 + (tid >> 3);
    int part = tid & 7;

    u64 ki = (i < cnt) ? g_keys[i] : ~0ull;
    int rank_all = 0, rank_act = 0;

    for (int base = 0; base < cnt; base += 2048) {
        int lim = min(2048, cnt - base);
        __syncthreads();
        for (int t = tid; t < lim; t += 256) sk[t] = g_keys[base + t];
        __syncthreads();
        for (int j = part; j < lim; j += 8) {
            u64 kj = sk[j];
            int lt = kj < ki;                      // full-u64 compare, no masking
            rank_all += lt;
            rank_act += lt & (int)(kj & 1ull);
        }
    }
    #pragma unroll
    for (int o = 1; o < 8; o <<= 1) {
        rank_all += __shfl_xor_sync(0xffffffffu, rank_all, o);
        rank_act += __shfl_xor_sync(0xffffffffu, rank_act, o);
    }

    if (part == 0 && i < cnt) {
        int o = (int)((ki >> 1) & 0x1FFFull);
        bool act = (ki & 1ull) != 0ull;
        float x1 = g_x1[o], y1 = g_y1[o], x2 = g_x2[o], y2 = g_y2[o], s = g_sc[o];
        if (act) {
            int r = rank_act;
            g_sx1[r]=x1; g_sy1[r]=y1; g_sx2[r]=x2; g_sy2[r]=y2;
            g_ssc[r]=s;  g_sar[r]=(x2-x1)*(y2-y1);
            g_apos[r]=rank_all;
        } else {
            float f = (g_maxbox <= 0xBF800000u) ? 1.0f : (1.0f / 416.0f);
            float* o6 = out + rank_all * 6;
            o6[0]=x1*f; o6[1]=y1*f; o6[2]=x2*f; o6[3]=y2*f; o6[4]=s; o6[5]=0.0f;
        }
    }
}

// pairwise IoU bitmask among actives: grid-stride over actual upper-triangle tiles
__global__ __launch_bounds__(256) void k_mask() {
    int cnt = g_cnt_a;
    if (cnt == 0) return;
    int W = (cnt + 63) >> 6;
    int itiles = (cnt + 15) >> 4;
    int wtiles = (W + 15) >> 4;
    int ntiles = itiles * wtiles;

    __shared__ float jx1[1040], jy1[1040], jx2[1040], jy2[1040], jar[1040];
    int tid = threadIdx.x;

    for (int t = blockIdx.x; t < ntiles; t += gridDim.x) {
        int i0 = (t / wtiles) * 16;
        int w0 = (t % wtiles) * 16;
        if ((w0 + 16) * 64 <= i0) continue;   // fully below diagonal (uniform per block)

        __syncthreads();                       // smem reuse guard
        for (int tt = tid; tt < 1024; tt += 256) {
            int j = w0 * 64 + tt;
            int jm = (tt >> 6) * 65 + (tt & 63);   // +1 pad per 64 -> conflict-free
            bool ok = j < cnt;
            jx1[jm] = ok ? g_sx1[j] :  3.4e38f;
            jy1[jm] = ok ? g_sy1[j] :  3.4e38f;
            jx2[jm] = ok ? g_sx2[j] : -3.4e38f;
            jy2[jm] = ok ? g_sy2[j] : -3.4e38f;
            jar[jm] = ok ? g_sar[j] : 0.0f;
        }
        __syncthreads();

        int r  = tid >> 4;          // row within tile
        int wl = tid & 15;          // word within tile
        int i = i0 + r;
        int w = w0 + wl;
        if (i < cnt && w < W) {
            float ix1 = g_sx1[i], iy1 = g_sy1[i], ix2 = g_sx2[i], iy2 = g_sy2[i], iar = g_sar[i];
            int base = wl * 65;
            u64 bits = 0;
            #pragma unroll 8
            for (int jj = 0; jj < 64; jj++) {
                float bx1 = jx1[base + jj], by1 = jy1[base + jj];
                float bx2 = jx2[base + jj], by2 = jy2[base + jj], ba = jar[base + jj];
                float xx1 = fmaxf(ix1, bx1), yy1 = fmaxf(iy1, by1);
                float xx2 = fminf(ix2, bx2), yy2 = fminf(iy2, by2);
                float dx = fmaxf(xx2 - xx1, 0.0f), dy = fmaxf(yy2 - yy1, 0.0f);
                float inter = dx * dy;
                float uni = iar + ba - inter;
                bool pred = (inter > 0.45f * uni) && (uni > 0.0f);
                bits |= ((u64)pred) << jj;
            }
            g_mask[(size_t)i * NW + w] = bits;
        }
    }
}

// greedy scan with the ENTIRE live mask staged in shared memory.
// One coalesced global burst up front; then all chunk iterations run on-chip:
// ballot fixed-point resolve (LDS) + apply (LDS + smem atomicOr) + emit.
// Falls back to global-memory reads if the mask exceeds the smem budget.
__global__ __launch_bounds__(256) void k_scan(float* __restrict__ out) {
    extern __shared__ u64 smask[];           // staged mask: smask[r*W + w]
    __shared__ u64 s_remv[NW];
    __shared__ u64 s_kb;
    int tid = threadIdx.x;
    int cnt = g_cnt_a;
    int W = (cnt + 63) >> 6;
    float f = (g_maxbox <= 0xBF800000u) ? 1.0f : (1.0f / 416.0f);

    bool fits = ((long long)cnt * W) <= SCAN_SMEM_WORDS;
    const u64* mptr;
    int stride;
    if (fits) {
        int total = cnt * W;
        for (int idx = tid; idx < total; idx += 256) {
            int r = idx / W;
            int w = idx - r * W;
            smask[idx] = g_mask[(size_t)r * NW + w];
        }
        mptr = smask; stride = W;
    } else {
        mptr = g_mask; stride = NW;          // correctness fallback (never for this data)
    }
    for (int w = tid; w < NW; w += 256) s_remv[w] = 0ull;
    __syncthreads();

    for (int c = 0; c < W; c++) {
        if (tid < 32) {
            // warp-parallel fixed-point resolve of chunk c (== greedy, proven R7/8)
            int l = tid;
            u64 sup = s_remv[c];
            int lim = cnt - c * 64;
            if (lim < 64) sup |= ~((1ull << lim) - 1ull);   // tail rows = suppressed
            int r_lo = c * 64 + l, r_hi = r_lo + 32;
            u64 d_lo = (r_lo < cnt) ? mptr[(size_t)r_lo * stride + c] : 0ull;
            u64 d_hi = (r_hi < cnt) ? mptr[(size_t)r_hi * stride + c] : 0ull;
            u32 cand_lo = (u32)((sup >> l) & 1ull) ^ 1u;
            u32 cand_hi = (u32)((sup >> (l + 32)) & 1ull) ^ 1u;
            u64 below_lo = (1ull << l) - 1ull;
            u64 below_hi = (1ull << (l + 32)) - 1ull;

            u32 kl = __ballot_sync(0xffffffffu, cand_lo);
            u32 kh = __ballot_sync(0xffffffffu, cand_hi);
            while (true) {
                u64 kept = (u64)kl | ((u64)kh << 32);
                u32 nl = __ballot_sync(0xffffffffu,
                        cand_lo && ((d_lo & kept & below_lo) == 0ull));
                kept = (u64)nl | ((u64)kh << 32);            // Gauss-Seidel for hi half
                u32 nh = __ballot_sync(0xffffffffu,
                        cand_hi && ((d_hi & kept & below_hi) == 0ull));
                bool stable = (nl == kl) && (nh == kh);
                kl = nl; kh = nh;
                if (stable) break;                           // fixed point == greedy
            }
            if (tid == 0) s_kb = (u64)kl | ((u64)kh << 32);
        }
        __syncthreads();
        u64 kb = s_kb;

        // emit kept rows of this chunk (fire-and-forget STGs)
        if (tid < 64) {
            int k = c * 64 + tid;
            if (k < cnt && ((kb >> tid) & 1ull)) {
                float* o = out + g_apos[k] * 6;
                *(float2*)(o)     = make_float2(g_sx1[k] * f, g_sy1[k] * f);
                *(float2*)(o + 2) = make_float2(g_sx2[k] * f, g_sy2[k] * f);
                *(float2*)(o + 4) = make_float2(g_ssc[k], 0.0f);
            }
        }

        // apply kb to all future words, entirely from smem: 16 w-slots x 16 row-groups
        int g = tid >> 4;                    // 0..15, 4 rows each
        size_t base = (size_t)c * 64;
        for (int w = (tid & 15); w < W; w += 16) {
            if (w > c) {
                u64 acc = 0;
                #pragma unroll
                for (int b2 = 0; b2 < 4; b2++) {
                    int b = g * 4 + b2;
                    acc |= mptr[(base + b) * stride + w] & (0ull - ((kb >> b) & 1ull));
                }
                if (acc) atomicOr(&s_remv[w], acc);
            }
        }
        __syncthreads();
    }

    // reset counters for the next graph replay
    if (tid == 0) { g_cnt = 0; g_cnt_a = 0; g_maxbox = 0u; }
}

extern "C" void kernel_launch(void* const* d_in, const int* in_sizes, int n_in,
                              void* d_out, int out_size) {
    const float* preds = (const float*)d_in[0];
    float* out = (float*)d_out;

    cudaFuncSetAttribute(k_scan, cudaFuncAttributeMaxDynamicSharedMemorySize,
                         SCAN_SMEM_WORDS * sizeof(u64));

    k_prep<<<N / 256, 256>>>(preds, out);
    k_rank<<<256, 256>>>(out);          // 32 i per block; excess blocks exit
    k_mask<<<128, 256>>>();
    k_scan<<<1, 256, SCAN_SMEM_WORDS * sizeof(u64)>>>(out);
}